// round 11
// baseline (speedup 1.0000x reference)
#include <cuda_runtime.h>
#include <cstdint>

// Chamfer distance, B=8, D=3, N=4096, fp32.
// R11: balanced tiling (16,16,8): CT=256 (4 warps share cols), RT=256 (warp
// owns 64 rows). Intermediates 16+16 slices = 4MB (vs 8.5MB). Col-min combine
// overlaid on spart SMEM. Main loop identical math to R8 (at fma-pipe wall).

#define NN 4096
#define BB 8
#define RT 256        // rows per block (64 per warp)
#define CT 256        // cols per block (8 per lane, shared by all warps)
#define NSLICE 16     // gx row slices
#define NPART 16      // gy col parts
#define RBLOCKS 128

__device__ float g_rowslice[NSLICE * BB * NN];
__device__ float g_colpart[NPART * BB * NN];
__device__ double g_bsum[RBLOCKS];
__device__ unsigned g_ticket;   // zero-init; last reduce block resets to 0

typedef unsigned long long u64;

__device__ __forceinline__ u64 pack2(float a, float b) {
    u64 r; asm("mov.b64 %0,{%1,%2};" : "=l"(r) : "f"(a), "f"(b)); return r;
}
__device__ __forceinline__ void unpack2(u64 v, float& a, float& b) {
    asm("mov.b64 {%0,%1},%2;" : "=f"(a), "=f"(b) : "l"(v));
}
__device__ __forceinline__ u64 add2(u64 a, u64 b) {
    u64 r; asm("add.rn.f32x2 %0,%1,%2;" : "=l"(r) : "l"(a), "l"(b)); return r;
}
__device__ __forceinline__ u64 fma2(u64 a, u64 b, u64 c) {
    u64 r; asm("fma.rn.f32x2 %0,%1,%2,%3;" : "=l"(r) : "l"(a), "l"(b), "l"(c)); return r;
}

__global__ __launch_bounds__(128, 8) void cd_main_kernel(
    const float* __restrict__ srcs, const float* __restrict__ tgts) {
    __shared__ __align__(16) float smrow[RT * 8];    // 8KB dup source rows
    __shared__ float spart[4 * 32 * 33];              // 16.9KB; overlaid later

    const int b    = blockIdx.z;
    const int r0   = blockIdx.y * RT;
    const int c0   = blockIdx.x * CT;
    const int tid  = threadIdx.x;
    const int w    = tid >> 5;
    const int lane = tid & 31;

    // stage 256 source rows: (-x,-x,-y,-y)(-z,-z,hrs,hrs); 2 rows per thread
    const float* sb = srcs + (size_t)b * 3 * NN;
    #pragma unroll
    for (int k = 0; k < 2; ++k) {
        const int rr = tid + k * 128;
        const int i = r0 + rr;
        const float x = sb[i], y = sb[NN + i], z = sb[2 * NN + i];
        const float hrs = 0.5f * (x * x + y * y + z * z);
        float4* p = reinterpret_cast<float4*>(smrow + rr * 8);
        p[0] = make_float4(-x, -x, -y, -y);
        p[1] = make_float4(-z, -z, hrs, hrs);
    }
    __syncthreads();

    // per-lane targets: 8 consecutive columns (same for all warps)
    const int col0 = c0 + lane * 8;
    const float* tb = tgts + (size_t)b * 3 * NN;
    const float4 X0 = *reinterpret_cast<const float4*>(tb + col0);
    const float4 X1 = *reinterpret_cast<const float4*>(tb + col0 + 4);
    const float4 Y0 = *reinterpret_cast<const float4*>(tb + NN + col0);
    const float4 Y1 = *reinterpret_cast<const float4*>(tb + NN + col0 + 4);
    const float4 Z0 = *reinterpret_cast<const float4*>(tb + 2 * NN + col0);
    const float4 Z1 = *reinterpret_cast<const float4*>(tb + 2 * NN + col0 + 4);

    const u64 tx0 = pack2(X0.x, X0.y), tx1 = pack2(X0.z, X0.w);
    const u64 tx2 = pack2(X1.x, X1.y), tx3 = pack2(X1.z, X1.w);
    const u64 ty0 = pack2(Y0.x, Y0.y), ty1 = pack2(Y0.z, Y0.w);
    const u64 ty2 = pack2(Y1.x, Y1.y), ty3 = pack2(Y1.z, Y1.w);
    const u64 tz0 = pack2(Z0.x, Z0.y), tz1 = pack2(Z0.z, Z0.w);
    const u64 tz2 = pack2(Z1.x, Z1.y), tz3 = pack2(Z1.z, Z1.w);
    const u64 hrt0 = pack2(0.5f*(X0.x*X0.x + Y0.x*Y0.x + Z0.x*Z0.x),
                           0.5f*(X0.y*X0.y + Y0.y*Y0.y + Z0.y*Z0.y));
    const u64 hrt1 = pack2(0.5f*(X0.z*X0.z + Y0.z*Y0.z + Z0.z*Z0.z),
                           0.5f*(X0.w*X0.w + Y0.w*Y0.w + Z0.w*Z0.w));
    const u64 hrt2 = pack2(0.5f*(X1.x*X1.x + Y1.x*Y1.x + Z1.x*Z1.x),
                           0.5f*(X1.y*X1.y + Y1.y*Y1.y + Z1.y*Z1.y));
    const u64 hrt3 = pack2(0.5f*(X1.z*X1.z + Y1.z*Y1.z + Z1.z*Z1.z),
                           0.5f*(X1.w*X1.w + Y1.w*Y1.w + Z1.w*Z1.w));

    const float INF = __int_as_float(0x7F800000);
    float cm0 = INF, cm1 = INF, cm2 = INF, cm3 = INF;
    float cm4 = INF, cm5 = INF, cm6 = INF, cm7 = INF;

    float* myPart = spart + w * (32 * 33);
    const int wr0 = w * 64;                 // this warp's first row in tile
    float* rowOut = g_rowslice + (size_t)blockIdx.x * (BB * NN) + b * NN + r0 + wr0;

    for (int rc = 0; rc < 64; rc += 32) {   // warp's 64 rows in two chunks
        const float* rp = smrow + (wr0 + rc) * 8;
        #pragma unroll 8
        for (int rr = 0; rr < 32; ++rr) {
            const ulonglong2 A  = *reinterpret_cast<const ulonglong2*>(rp + rr * 8);
            const ulonglong2 Bq = *reinterpret_cast<const ulonglong2*>(rp + rr * 8 + 4);
            u64 d0 = add2(Bq.y, hrt0);
            u64 d1 = add2(Bq.y, hrt1);
            u64 d2 = add2(Bq.y, hrt2);
            u64 d3 = add2(Bq.y, hrt3);
            d0 = fma2(A.x, tx0, d0);  d1 = fma2(A.x, tx1, d1);
            d2 = fma2(A.x, tx2, d2);  d3 = fma2(A.x, tx3, d3);
            d0 = fma2(A.y, ty0, d0);  d1 = fma2(A.y, ty1, d1);
            d2 = fma2(A.y, ty2, d2);  d3 = fma2(A.y, ty3, d3);
            d0 = fma2(Bq.x, tz0, d0); d1 = fma2(Bq.x, tz1, d1);
            d2 = fma2(Bq.x, tz2, d2); d3 = fma2(Bq.x, tz3, d3);
            float f0, f1, f2, f3, f4, f5, f6, f7;
            unpack2(d0, f0, f1); unpack2(d1, f2, f3);
            unpack2(d2, f4, f5); unpack2(d3, f6, f7);
            cm0 = fminf(cm0, f0); cm1 = fminf(cm1, f1);
            cm2 = fminf(cm2, f2); cm3 = fminf(cm3, f3);
            cm4 = fminf(cm4, f4); cm5 = fminf(cm5, f5);
            cm6 = fminf(cm6, f6); cm7 = fminf(cm7, f7);
            const float p01 = fminf(f0, f1), p23 = fminf(f2, f3);
            const float p45 = fminf(f4, f5), p67 = fminf(f6, f7);
            myPart[lane * 33 + rr] = fminf(fminf(p01, p23), fminf(p45, p67));
        }
        __syncwarp();
        // transpose reduce: lane L reduces row rc+L across 32 lanes
        float ma = myPart[lane];
        float mb = myPart[16 * 33 + lane];
        #pragma unroll
        for (int k = 1; k < 16; ++k) {
            ma = fminf(ma, myPart[k * 33 + lane]);
            mb = fminf(mb, myPart[(k + 16) * 33 + lane]);
        }
        rowOut[rc + lane] = fminf(ma, mb);   // warp-exclusive rows: plain STG
        __syncwarp();
    }

    // ---- col-min cross-warp combine, overlaid on spart (all uses done) ----
    __syncthreads();
    float* overlay = spart;                  // 4 warps x 256 floats = 4KB
    float* mine = overlay + w * CT + lane * 8;
    mine[0] = cm0; mine[1] = cm1; mine[2] = cm2; mine[3] = cm3;
    mine[4] = cm4; mine[5] = cm5; mine[6] = cm6; mine[7] = cm7;
    __syncthreads();
    float* cp = g_colpart + (size_t)blockIdx.y * (BB * NN) + b * NN + c0;
    #pragma unroll
    for (int c = tid; c < CT; c += 128) {
        const float m = fminf(fminf(overlay[c],          overlay[CT + c]),
                              fminf(overlay[2 * CT + c], overlay[3 * CT + c]));
        cp[c] = m;
    }
}

// merged reduction: 128 blocks x 256 threads; 32 loads/thread (4MB total).
__global__ __launch_bounds__(256) void cd_reduce_kernel(float* __restrict__ out) {
    __shared__ float swarp[8];
    __shared__ double dsum[4];
    __shared__ bool amLast;
    const int tid = threadIdx.x;
    const int g   = blockIdx.x * 256 + tid;   // 0..32767

    float a0 = g_rowslice[g];
    float a1 = g_rowslice[1 * (BB * NN) + g];
    float a2 = g_rowslice[2 * (BB * NN) + g];
    float a3 = g_rowslice[3 * (BB * NN) + g];
    float b0 = g_colpart[g];
    float b1 = g_colpart[1 * (BB * NN) + g];
    float b2 = g_colpart[2 * (BB * NN) + g];
    float b3 = g_colpart[3 * (BB * NN) + g];
    #pragma unroll
    for (int p = 4; p < NSLICE; p += 4) {
        a0 = fminf(a0, g_rowslice[(p + 0) * (BB * NN) + g]);
        a1 = fminf(a1, g_rowslice[(p + 1) * (BB * NN) + g]);
        a2 = fminf(a2, g_rowslice[(p + 2) * (BB * NN) + g]);
        a3 = fminf(a3, g_rowslice[(p + 3) * (BB * NN) + g]);
        b0 = fminf(b0, g_colpart[(p + 0) * (BB * NN) + g]);
        b1 = fminf(b1, g_colpart[(p + 1) * (BB * NN) + g]);
        b2 = fminf(b2, g_colpart[(p + 2) * (BB * NN) + g]);
        b3 = fminf(b3, g_colpart[(p + 3) * (BB * NN) + g]);
    }
    const float v  = fminf(fminf(a0, a1), fminf(a2, a3));
    const float v2 = fminf(fminf(b0, b1), fminf(b2, b3));

    float s = 2.0f * (v + v2);   // undo h = d/2 scaling
    #pragma unroll
    for (int o = 16; o; o >>= 1) s += __shfl_down_sync(0xffffffff, s, o);
    if ((tid & 31) == 0) swarp[tid >> 5] = s;
    __syncthreads();
    if (tid < 32) {
        float t = (tid < 8) ? swarp[tid] : 0.f;
        #pragma unroll
        for (int o = 4; o; o >>= 1) t += __shfl_down_sync(0xffffffff, t, o);
        if (tid == 0) {
            g_bsum[blockIdx.x] = (double)t;
            __threadfence();
            unsigned done = atomicAdd(&g_ticket, 1u);
            amLast = (done == RBLOCKS - 1);
        }
    }
    __syncthreads();
    if (amLast) {
        if (tid < RBLOCKS) {
            double dd = g_bsum[tid];
            #pragma unroll
            for (int o = 16; o; o >>= 1) dd += __shfl_down_sync(0xffffffff, dd, o);
            if ((tid & 31) == 0) dsum[tid >> 5] = dd;
        }
        __syncthreads();
        if (tid == 0) {
            out[0] = (float)((dsum[0] + dsum[1] + dsum[2] + dsum[3]) /
                             (double)(BB * NN));
            g_ticket = 0u;   // reset for next graph replay
        }
    }
}

extern "C" void kernel_launch(void* const* d_in, const int* in_sizes, int n_in,
                              void* d_out, int out_size) {
    const float* srcs = (const float*)d_in[0];
    const float* tgts = (const float*)d_in[1];
    float* out = (float*)d_out;

    dim3 grid(NN / CT, NN / RT, BB);  // (16, 16, 8) = 2048 blocks
    cd_main_kernel<<<grid, 128>>>(srcs, tgts);
    cd_reduce_kernel<<<RBLOCKS, 256>>>(out);
}

// round 12
// speedup vs baseline: 1.0585x; 1.0585x over previous
#include <cuda_runtime.h>
#include <cstdint>

// Chamfer distance, B=8, D=3, N=4096, fp32.
// R12: single fused kernel. R10 main body (grid 2048, CT=1024, 8 cols/lane,
// warp-combined row slices NSLICE=4, col parts NPART=64) + in-kernel
// reduction: double-ticket scheme, last 256 arrivals become reducer blocks
// (reduce kernel was launch/ramp-floored ~7us regardless of traffic).

#define NN 4096
#define BB 8
#define RT 64         // source rows per block
#define CT 1024       // target cols per block = 4 warps * 256
#define NSLICE 4      // row slices (one per coltile, warp-combined)
#define NPART 64      // col parts (one per rowtile)
#define TOTAL 2048    // total blocks
#define RED 256       // reducer blocks (last RED arrivals)

__device__ float g_rowslice[NSLICE * BB * NN];
__device__ float g_colpart[NPART * BB * NN];
__device__ double g_bsum[RED];
__device__ unsigned g_ticket1;   // zero-init; final block resets
__device__ unsigned g_ticket2;   // zero-init; final block resets

typedef unsigned long long u64;

__device__ __forceinline__ u64 pack2(float a, float b) {
    u64 r; asm("mov.b64 %0,{%1,%2};" : "=l"(r) : "f"(a), "f"(b)); return r;
}
__device__ __forceinline__ void unpack2(u64 v, float& a, float& b) {
    asm("mov.b64 {%0,%1},%2;" : "=f"(a), "=f"(b) : "l"(v));
}
__device__ __forceinline__ u64 add2(u64 a, u64 b) {
    u64 r; asm("add.rn.f32x2 %0,%1,%2;" : "=l"(r) : "l"(a), "l"(b)); return r;
}
__device__ __forceinline__ u64 fma2(u64 a, u64 b, u64 c) {
    u64 r; asm("fma.rn.f32x2 %0,%1,%2,%3;" : "=l"(r) : "l"(a), "l"(b), "l"(c)); return r;
}

__global__ __launch_bounds__(128, 8) void cd_fused_kernel(
    const float* __restrict__ srcs, const float* __restrict__ tgts,
    float* __restrict__ out) {
    __shared__ __align__(16) float smrow[RT * 8];   // (-x,-x,-y,-y)(-z,-z,hrs,hrs)
    __shared__ float spart[4][32 * 33];
    __shared__ float scomb[4][RT];
    __shared__ unsigned myDone;
    __shared__ bool amLast;
    __shared__ double dsum[4];

    const int b    = blockIdx.z;
    const int r0   = blockIdx.y * RT;
    const int c0   = blockIdx.x * CT;
    const int tid  = threadIdx.x;
    const int w    = tid >> 5;
    const int lane = tid & 31;

    const float* sb = srcs + (size_t)b * 3 * NN;
    if (tid < RT) {
        const int i = r0 + tid;
        const float x = sb[i], y = sb[NN + i], z = sb[2 * NN + i];
        const float hrs = 0.5f * (x * x + y * y + z * z);
        float4* p = reinterpret_cast<float4*>(smrow + tid * 8);
        p[0] = make_float4(-x, -x, -y, -y);
        p[1] = make_float4(-z, -z, hrs, hrs);
    }
    __syncthreads();

    const int col0 = c0 + w * 256 + lane * 8;
    const float* tb = tgts + (size_t)b * 3 * NN;
    const float4 X0 = *reinterpret_cast<const float4*>(tb + col0);
    const float4 X1 = *reinterpret_cast<const float4*>(tb + col0 + 4);
    const float4 Y0 = *reinterpret_cast<const float4*>(tb + NN + col0);
    const float4 Y1 = *reinterpret_cast<const float4*>(tb + NN + col0 + 4);
    const float4 Z0 = *reinterpret_cast<const float4*>(tb + 2 * NN + col0);
    const float4 Z1 = *reinterpret_cast<const float4*>(tb + 2 * NN + col0 + 4);

    const u64 tx0 = pack2(X0.x, X0.y), tx1 = pack2(X0.z, X0.w);
    const u64 tx2 = pack2(X1.x, X1.y), tx3 = pack2(X1.z, X1.w);
    const u64 ty0 = pack2(Y0.x, Y0.y), ty1 = pack2(Y0.z, Y0.w);
    const u64 ty2 = pack2(Y1.x, Y1.y), ty3 = pack2(Y1.z, Y1.w);
    const u64 tz0 = pack2(Z0.x, Z0.y), tz1 = pack2(Z0.z, Z0.w);
    const u64 tz2 = pack2(Z1.x, Z1.y), tz3 = pack2(Z1.z, Z1.w);
    const u64 hrt0 = pack2(0.5f*(X0.x*X0.x + Y0.x*Y0.x + Z0.x*Z0.x),
                           0.5f*(X0.y*X0.y + Y0.y*Y0.y + Z0.y*Z0.y));
    const u64 hrt1 = pack2(0.5f*(X0.z*X0.z + Y0.z*Y0.z + Z0.z*Z0.z),
                           0.5f*(X0.w*X0.w + Y0.w*Y0.w + Z0.w*Z0.w));
    const u64 hrt2 = pack2(0.5f*(X1.x*X1.x + Y1.x*Y1.x + Z1.x*Z1.x),
                           0.5f*(X1.y*X1.y + Y1.y*Y1.y + Z1.y*Z1.y));
    const u64 hrt3 = pack2(0.5f*(X1.z*X1.z + Y1.z*Y1.z + Z1.z*Z1.z),
                           0.5f*(X1.w*X1.w + Y1.w*Y1.w + Z1.w*Z1.w));

    const float INF = __int_as_float(0x7F800000);
    float cm0 = INF, cm1 = INF, cm2 = INF, cm3 = INF;
    float cm4 = INF, cm5 = INF, cm6 = INF, cm7 = INF;

    float* myPart = &spart[w][0];

    for (int rc = 0; rc < RT; rc += 32) {
        const float* rp = smrow + rc * 8;
        #pragma unroll 8
        for (int rr = 0; rr < 32; ++rr) {
            const ulonglong2 A  = *reinterpret_cast<const ulonglong2*>(rp + rr * 8);
            const ulonglong2 Bq = *reinterpret_cast<const ulonglong2*>(rp + rr * 8 + 4);
            u64 d0 = add2(Bq.y, hrt0);
            u64 d1 = add2(Bq.y, hrt1);
            u64 d2 = add2(Bq.y, hrt2);
            u64 d3 = add2(Bq.y, hrt3);
            d0 = fma2(A.x, tx0, d0);  d1 = fma2(A.x, tx1, d1);
            d2 = fma2(A.x, tx2, d2);  d3 = fma2(A.x, tx3, d3);
            d0 = fma2(A.y, ty0, d0);  d1 = fma2(A.y, ty1, d1);
            d2 = fma2(A.y, ty2, d2);  d3 = fma2(A.y, ty3, d3);
            d0 = fma2(Bq.x, tz0, d0); d1 = fma2(Bq.x, tz1, d1);
            d2 = fma2(Bq.x, tz2, d2); d3 = fma2(Bq.x, tz3, d3);
            float f0, f1, f2, f3, f4, f5, f6, f7;
            unpack2(d0, f0, f1); unpack2(d1, f2, f3);
            unpack2(d2, f4, f5); unpack2(d3, f6, f7);
            cm0 = fminf(cm0, f0); cm1 = fminf(cm1, f1);
            cm2 = fminf(cm2, f2); cm3 = fminf(cm3, f3);
            cm4 = fminf(cm4, f4); cm5 = fminf(cm5, f5);
            cm6 = fminf(cm6, f6); cm7 = fminf(cm7, f7);
            const float p01 = fminf(f0, f1), p23 = fminf(f2, f3);
            const float p45 = fminf(f4, f5), p67 = fminf(f6, f7);
            myPart[lane * 33 + rr] = fminf(fminf(p01, p23), fminf(p45, p67));
        }
        __syncwarp();
        float ma = myPart[lane];
        float mb = myPart[16 * 33 + lane];
        #pragma unroll
        for (int k = 1; k < 16; ++k) {
            ma = fminf(ma, myPart[k * 33 + lane]);
            mb = fminf(mb, myPart[(k + 16) * 33 + lane]);
        }
        scomb[w][rc + lane] = fminf(ma, mb);
        __syncwarp();
    }

    __syncthreads();
    if (tid < RT) {
        const float m = fminf(fminf(scomb[0][tid], scomb[1][tid]),
                              fminf(scomb[2][tid], scomb[3][tid]));
        g_rowslice[(size_t)blockIdx.x * (BB * NN) + b * NN + r0 + tid] = m;
    }
    float* cp = g_colpart + (size_t)blockIdx.y * (BB * NN) + b * NN + col0;
    *reinterpret_cast<float4*>(cp)     = make_float4(cm0, cm1, cm2, cm3);
    *reinterpret_cast<float4*>(cp + 4) = make_float4(cm4, cm5, cm6, cm7);

    // ---- ticket 1: publish slices, last RED arrivals become reducers ----
    __threadfence();
    __syncthreads();
    if (tid == 0) myDone = atomicAdd(&g_ticket1, 1u);
    __syncthreads();
    if (myDone < TOTAL - RED) return;

    // spin until every block has published
    if (tid == 0) {
        while (*(volatile unsigned*)&g_ticket1 < TOTAL) __nanosleep(64);
    }
    __syncthreads();
    __threadfence();   // acquire published slices

    // ---- reduce phase: rid in [0, RED), 128 elements per reducer ----
    const int rid = (int)myDone - (TOTAL - RED);
    const int g   = rid * 128 + tid;          // 0..32767 = b*N + idx

    float v = fminf(fminf(g_rowslice[g],                 g_rowslice[1 * (BB * NN) + g]),
                    fminf(g_rowslice[2 * (BB * NN) + g], g_rowslice[3 * (BB * NN) + g]));
    float a0 = g_colpart[g];
    float a1 = g_colpart[1 * (BB * NN) + g];
    float a2 = g_colpart[2 * (BB * NN) + g];
    float a3 = g_colpart[3 * (BB * NN) + g];
    #pragma unroll
    for (int p = 4; p < NPART; p += 4) {
        a0 = fminf(a0, g_colpart[(p + 0) * (BB * NN) + g]);
        a1 = fminf(a1, g_colpart[(p + 1) * (BB * NN) + g]);
        a2 = fminf(a2, g_colpart[(p + 2) * (BB * NN) + g]);
        a3 = fminf(a3, g_colpart[(p + 3) * (BB * NN) + g]);
    }
    const float v2 = fminf(fminf(a0, a1), fminf(a2, a3));

    float s = 2.0f * (v + v2);   // undo h = d/2 scaling
    #pragma unroll
    for (int o = 16; o; o >>= 1) s += __shfl_down_sync(0xffffffff, s, o);
    if ((tid & 31) == 0) scomb[0][tid >> 5] = s;   // reuse smem
    __syncthreads();
    if (tid == 0) {
        const double t = (double)(scomb[0][0] + scomb[0][1] +
                                  scomb[0][2] + scomb[0][3]);
        g_bsum[rid] = t;
        __threadfence();
        const unsigned d2 = atomicAdd(&g_ticket2, 1u);
        amLast = (d2 == RED - 1);
    }
    __syncthreads();
    if (!amLast) return;

    // ---- final: sum 256 partials with 128 threads ----
    {
        double dd = g_bsum[tid] + g_bsum[tid + 128];
        #pragma unroll
        for (int o = 16; o; o >>= 1) dd += __shfl_down_sync(0xffffffff, dd, o);
        if ((tid & 31) == 0) dsum[tid >> 5] = dd;
        __syncthreads();
        if (tid == 0) {
            out[0] = (float)((dsum[0] + dsum[1] + dsum[2] + dsum[3]) /
                             (double)(BB * NN));
            g_ticket1 = 0u;   // reset for next graph replay
            g_ticket2 = 0u;
        }
    }
}

extern "C" void kernel_launch(void* const* d_in, const int* in_sizes, int n_in,
                              void* d_out, int out_size) {
    const float* srcs = (const float*)d_in[0];
    const float* tgts = (const float*)d_in[1];
    float* out = (float*)d_out;

    dim3 grid(NN / CT, NN / RT, BB);  // (4, 64, 8) = 2048 blocks
    cd_fused_kernel<<<grid, 128>>>(srcs, tgts, out);
}